// round 14
// baseline (speedup 1.0000x reference)
#include <cuda_runtime.h>
#include <math.h>

// Fused DTCWT scattering layer, round 14: warp-autonomous + load-balanced staging + full unroll.
//  - each warp owns 32 pair-columns; private 16-slot smem ring of 80-float segments
//  - staging spread evenly: 5 x 16B cp.async per lane per 8 rows (all 32 lanes)
//  - edge halos (warps 0,7): 2 x 4B reflected cp.async per lane
//  - no __syncthreads anywhere; wait_group + __syncwarp only
//  - main loop fully unrolled: all ring offsets/indices compile-time
// x: (32,3,512,512) f32 -> out: (32,21,256,256) f32

#define TILE_OY 16
#define NTHREADS 256
#define NWARP 8
#define SEGW 80                    // 8 halo | 64 data | 8 halo (floats)
#define NSLOT 16
#define SMEM_BYTES (NWARP*NSLOT*SEGW*4)   // 40960

// h0: [-0.05, 0.25, 0.6, 0.25, -0.05]  (symmetric)
#define G0 (-0.05f)
#define G1 (0.25f)
#define G2 (0.6f)
// h1: [-0.0107143, 0.0535714, 0.2607143, -0.6071429, ...] (symmetric)
#define H0 (-0.0107143f)
#define H1 (0.0535714f)
#define H2 (0.2607143f)
#define H3 (-0.6071429f)

typedef unsigned long long u64;

__device__ __forceinline__ u64 pk(float lo, float hi) {
    u64 r; asm("mov.b64 %0,{%1,%2};" : "=l"(r) : "f"(lo), "f"(hi)); return r;
}
__device__ __forceinline__ void upk(u64 v, float& a, float& b) {
    asm("mov.b64 {%0,%1},%2;" : "=f"(a), "=f"(b) : "l"(v));
}
__device__ __forceinline__ u64 add2(u64 a, u64 b) {
    u64 r; asm("add.rn.f32x2 %0,%1,%2;" : "=l"(r) : "l"(a), "l"(b)); return r;
}
__device__ __forceinline__ u64 mul2(u64 a, u64 b) {
    u64 r; asm("mul.rn.f32x2 %0,%1,%2;" : "=l"(r) : "l"(a), "l"(b)); return r;
}
__device__ __forceinline__ u64 fma2(u64 a, u64 b, u64 c) {
    u64 r; asm("fma.rn.f32x2 %0,%1,%2,%3;" : "=l"(r) : "l"(a), "l"(b), "l"(c)); return r;
}

__device__ __forceinline__ int refl(int i) {
    i = (i < 0) ? (-i - 1) : i;
    return (i > 511) ? (1023 - i) : i;
}
__device__ __forceinline__ float sqrt_approx(float v) {
    float r; asm("sqrt.approx.f32 %0, %1;" : "=f"(r) : "f"(v)); return r;
}
// band value = sqrt((re^2+im^2)/2 + 1e-4) - 0.01  (1/sqrt2 folded in)
__device__ __forceinline__ float bandmag(float re, float im) {
    return sqrt_approx(0.5f * fmaf(re, re, fmaf(im, im, 2e-4f))) - 0.01f;
}

__device__ __forceinline__ void commit_group() {
    asm volatile("cp.async.commit_group;\n" ::: "memory");
}
__device__ __forceinline__ void wait_all() {
    asm volatile("cp.async.wait_group 0;\n" ::: "memory");
}

// Stage NR rows (window indices m0..m0+NR-1) into this warp's private ring,
// load-balanced: NR*20 16B chunks spread over 32 lanes; edge halos (NR*8 4B ops)
// spread over 32 lanes of warps 0/7. All async.
template<int NR>
__device__ __forceinline__ void stage_rows(const float* __restrict__ xin, float* seg,
                                           int lane, int wi, int R, int m0) {
    constexpr int TOT = NR * 20;
    #pragma unroll
    for (int k = 0; k < (TOT + 31) / 32; ++k) {
        const int idx = lane + 32*k;
        if ((TOT % 32) && idx >= TOT) continue;
        const int j  = idx / 20;            // row within batch
        const int ch = idx % 20;            // 16B chunk within segment
        const bool valid = (wi > 0 || ch >= 2) && (wi < 7 || ch < 18);
        const int gy = refl(R + m0 + j);
        if (valid) {
            const float* src = xin + (size_t)gy*512 + (64*wi - 8 + 4*ch);
            unsigned dst = (unsigned)__cvta_generic_to_shared(
                seg + ((m0 + j) & (NSLOT-1))*SEGW + 4*ch);
            asm volatile("cp.async.cg.shared.global [%0], [%1], 16;\n"
                         :: "r"(dst), "l"(src) : "memory");
        }
    }
    if (wi == 0 || wi == 7) {
        constexpr int HTOT = NR * 8;
        #pragma unroll
        for (int k = 0; k < (HTOT + 31) / 32; ++k) {
            const int idx = lane + 32*k;
            if ((HTOT % 32) && idx >= HTOT) continue;
            const int j = idx >> 3;         // row within batch
            const int f = idx & 7;          // halo float 0..7
            const int gy = refl(R + m0 + j);
            const int srccol = (wi == 0) ? (7 - f) : (511 - f);
            const int dstofs = (wi == 0) ? f : (72 + f);
            const float* src = xin + (size_t)gy*512 + srccol;
            unsigned dst = (unsigned)__cvta_generic_to_shared(
                seg + ((m0 + j) & (NSLOT-1))*SEGW + dstofs);
            asm volatile("cp.async.ca.shared.global [%0], [%1], 4;\n"
                         :: "r"(dst), "l"(src) : "memory");
        }
    }
}

// branch-free horizontal filters: p points at this thread's center pair (w3,w4)
__device__ __forceinline__ void hfilt_row(const float* __restrict__ p,
                                          u64 g0p, u64 g1p, u64 g2p,
                                          u64 h0p, u64 h1p, u64 h2p, u64 h3p,
                                          u64& loxy, u64& hizw) {
    const u64 PA = *(const u64*)(p - 4);
    const u64 PB = *(const u64*)(p - 2);
    const u64 PC = *(const u64*)(p    );
    const u64 PD = *(const u64*)(p + 2);
    const u64 PE = *(const u64*)(p + 4);
    float am, a0, b1, b2, c3, c4, d5, d6, e7, e8;
    upk(PA, am, a0); upk(PB, b1, b2); upk(PC, c3, c4);
    upk(PD, d5, d6); upk(PE, e7, e8);
    const u64 S1 = add2(PB, PD);                  // (w1+w5, w2+w6)
    const u64 S2 = pk(b2 + c4, c3 + d5);          // (w2+w4, w3+w5)
    const u64 T1 = pk(a0 + d6, b1 + e7);          // (w0+w6, w1+w7)
    loxy = fma2(S1, g0p, fma2(S2, g1p, mul2(PC, g2p)));
    hizw = fma2(T1, h0p, fma2(S1, h1p, fma2(S2, h2p, mul2(PC, h3p))));
}

__global__ __launch_bounds__(NTHREADS, 4) void scat_kernel(
    const float* __restrict__ x,
    float* __restrict__ out)
{
    extern __shared__ float smem[];        // [NWARP][NSLOT][SEGW]

    const int tid  = threadIdx.x;
    const int wi   = tid >> 5;
    const int lane = tid & 31;
    const int img  = blockIdx.z;
    const int OY0  = blockIdx.y * TILE_OY;
    const float* __restrict__ xin = x + (size_t)img * (512*512);
    float* seg = smem + wi * (NSLOT*SEGW);

    const int b_  = img / 3;
    const int ch_ = img % 3;
    const int c   = 32*wi + lane;
    float* o = out + (((size_t)b_*21 + ch_)*256 + OY0)*256 + c;
    const size_t cs = (size_t)3*256*256;

    const u64 g0p = pk(G0, G0), g1p = pk(G1, G1), g2p = pk(G2, G2);
    const u64 h0p = pk(H0, H0), h1p = pk(H1, H1), h2p = pk(H2, H2), h3p = pk(H3, H3);

    const int R = 2*OY0 - 3;               // input row = R + m, m = 0..37
    const int cofs = 8 + 2*lane;

    // ---- prologue: stage rows m=0..13, ring-fill m=0..5 (warp-local) ----
    stage_rows<14>(xin, seg, lane, wi, R, 0);
    commit_group();
    wait_all();
    __syncwarp();

    u64 rxy[8], rzw[8];
    #pragma unroll
    for (int j = 0; j < 6; j++)
        hfilt_row(seg + j*SEGW + cofs, g0p, g1p, g2p, h0p, h1p, h2p, h3p,
                  rxy[j], rzw[j]);

    #pragma unroll
    for (int i = 0; i < 4; ++i) {          // fully unrolled: all slots compile-time
        if (i > 0) {
            wait_all();
            __syncwarp();
        }
        if (i < 3) {
            stage_rows<8>(xin, seg, lane, wi, R, 14 + 8*i);
            commit_group();
        }

        #pragma unroll
        for (int u = 0; u < 4; ++u) {
            const int m6 = 8*i + 6 + 2*u;
            hfilt_row(seg + ((m6    ) & (NSLOT-1))*SEGW + cofs,
                      g0p, g1p, g2p, h0p, h1p, h2p, h3p,
                      rxy[(6 + 2*u) & 7], rzw[(6 + 2*u) & 7]);
            hfilt_row(seg + ((m6 + 1) & (NSLOT-1))*SEGW + cofs,
                      g0p, g1p, g2p, h0p, h1p, h2p, h3p,
                      rxy[(7 + 2*u) & 7], rzw[(7 + 2*u) & 7]);

            const int w0 = 2*u;

            float llp, m15, m165, m45, m135, m75, m105;
            #pragma unroll
            for (int plane = 0; plane < 2; plane++) {
                const u64* r = plane ? rzw : rxy;
                const u64 r0 = r[(w0 + 0) & 7], r1 = r[(w0 + 1) & 7];
                const u64 r2 = r[(w0 + 2) & 7], r3 = r[(w0 + 3) & 7];
                const u64 r4 = r[(w0 + 4) & 7], r5 = r[(w0 + 5) & 7];
                const u64 r6 = r[(w0 + 6) & 7], r7 = r[(w0 + 7) & 7];

                const u64 A06 = add2(r0, r6), A15 = add2(r1, r5), A24 = add2(r2, r4);
                const u64 A17 = add2(r1, r7), A26 = add2(r2, r6), A35 = add2(r3, r5);

                const u64 F0 = fma2(A06, h0p, fma2(A15, h1p, fma2(A24, h2p, mul2(r3, h3p))));
                const u64 F1 = fma2(A17, h0p, fma2(A26, h1p, fma2(A35, h2p, mul2(r4, h3p))));

                float f0x, f0y, f1x, f1y;
                upk(F0, f0x, f0y); upk(F1, f1x, f1y);

                if (plane == 0) {
                    m15  = bandmag(f0x - f1y, f0y + f1x);
                    m165 = bandmag(f0x + f1y, f0y - f1x);
                    const u64 B  = add2(A15, A26);
                    const u64 Cs = add2(A24, A35);
                    const u64 Ds = add2(r3, r4);
                    const u64 LLs = fma2(B, g0p, fma2(Cs, g1p, mul2(Ds, g2p)));
                    float s0, s1;
                    upk(LLs, s0, s1);
                    llp = 0.25f * (s0 + s1);
                } else {
                    m45  = bandmag(f0x - f1y, f0y + f1x);
                    m135 = bandmag(f0x + f1y, f0y - f1x);
                    const u64 E0 = fma2(A15, g0p, fma2(A24, g1p, mul2(r3, g2p)));
                    const u64 E1 = fma2(A26, g0p, fma2(A35, g1p, mul2(r4, g2p)));
                    float e0x, e0y, e1x, e1y;
                    upk(E0, e0x, e0y); upk(E1, e1x, e1y);
                    m75  = bandmag(e0x - e1y, e0y + e1x);
                    m105 = bandmag(e0x + e1y, e0y - e1x);
                }
            }

            o[0]    = llp;
            o[1*cs] = m15;
            o[2*cs] = m45;
            o[3*cs] = m75;
            o[4*cs] = m105;
            o[5*cs] = m135;
            o[6*cs] = m165;
            o += 256;
        }
    }
}

extern "C" void kernel_launch(void* const* d_in, const int* in_sizes, int n_in,
                              void* d_out, int out_size) {
    const float* x = (const float*)d_in[0];
    float* out = (float*)d_out;

    cudaFuncSetAttribute(scat_kernel,
                         cudaFuncAttributeMaxDynamicSharedMemorySize, SMEM_BYTES);

    dim3 grid(1, 256/TILE_OY, 96);         // (1, 16, 96)
    scat_kernel<<<grid, NTHREADS, SMEM_BYTES>>>(x, out);
}

// round 15
// speedup vs baseline: 1.1705x; 1.1705x over previous
#include <cuda_runtime.h>
#include <math.h>

// Fused DTCWT scattering layer, round 15: warp-autonomous + shift/mask-balanced staging.
//  - each warp owns 32 pair-columns; private 16-slot smem ring of 80-float segments
//  - staging: lane -> row j=lane>>2, chunks ch=(lane&3)+4t (5 x 16B cp.async/lane, no div/mod)
//  - edge halos (warps 0,7): 2 x 4B reflected cp.async per lane, same shift/mask mapping
//  - no __syncthreads; wait_group + __syncwarp only; outer loop NOT unrolled
// x: (32,3,512,512) f32 -> out: (32,21,256,256) f32

#define TILE_OY 16
#define NTHREADS 256
#define NWARP 8
#define SEGW 80                    // 8 halo | 64 data | 8 halo (floats)
#define NSLOT 16
#define SMEM_BYTES (NWARP*NSLOT*SEGW*4)   // 40960

// h0: [-0.05, 0.25, 0.6, 0.25, -0.05]  (symmetric)
#define G0 (-0.05f)
#define G1 (0.25f)
#define G2 (0.6f)
// h1: [-0.0107143, 0.0535714, 0.2607143, -0.6071429, ...] (symmetric)
#define H0 (-0.0107143f)
#define H1 (0.0535714f)
#define H2 (0.2607143f)
#define H3 (-0.6071429f)

typedef unsigned long long u64;

__device__ __forceinline__ u64 pk(float lo, float hi) {
    u64 r; asm("mov.b64 %0,{%1,%2};" : "=l"(r) : "f"(lo), "f"(hi)); return r;
}
__device__ __forceinline__ void upk(u64 v, float& a, float& b) {
    asm("mov.b64 {%0,%1},%2;" : "=f"(a), "=f"(b) : "l"(v));
}
__device__ __forceinline__ u64 add2(u64 a, u64 b) {
    u64 r; asm("add.rn.f32x2 %0,%1,%2;" : "=l"(r) : "l"(a), "l"(b)); return r;
}
__device__ __forceinline__ u64 mul2(u64 a, u64 b) {
    u64 r; asm("mul.rn.f32x2 %0,%1,%2;" : "=l"(r) : "l"(a), "l"(b)); return r;
}
__device__ __forceinline__ u64 fma2(u64 a, u64 b, u64 c) {
    u64 r; asm("fma.rn.f32x2 %0,%1,%2,%3;" : "=l"(r) : "l"(a), "l"(b), "l"(c)); return r;
}

__device__ __forceinline__ int refl(int i) {
    i = (i < 0) ? (-i - 1) : i;
    return (i > 511) ? (1023 - i) : i;
}
__device__ __forceinline__ float sqrt_approx(float v) {
    float r; asm("sqrt.approx.f32 %0, %1;" : "=f"(r) : "f"(v)); return r;
}
// band value = sqrt((re^2+im^2)/2 + 1e-4) - 0.01  (1/sqrt2 folded in)
__device__ __forceinline__ float bandmag(float re, float im) {
    return sqrt_approx(0.5f * fmaf(re, re, fmaf(im, im, 2e-4f))) - 0.01f;
}

__device__ __forceinline__ void commit_group() {
    asm volatile("cp.async.commit_group;\n" ::: "memory");
}
__device__ __forceinline__ void wait_all() {
    asm volatile("cp.async.wait_group 0;\n" ::: "memory");
}

// Stage 8 rows (window indices m0..m0+7) into this warp's private ring.
// lane -> row j = lane>>2 (4 lanes per row); each lane copies 5 16B chunks
// ch = (lane&3)+4t. One refl + one slot address per lane per call.
__device__ __forceinline__ void stage8(const float* __restrict__ xin, float* seg,
                                       int lane, int wi, int R, int m0) {
    const int j = lane >> 2;
    const int q = lane & 3;
    const int m = m0 + j;
    const int gy = refl(R + m);
    const float* rowp = xin + (size_t)gy * 512;
    float* slotp = seg + (m & (NSLOT-1)) * SEGW;

    #pragma unroll
    for (int t = 0; t < 5; ++t) {
        const int ch = q + 4*t;            // 16B chunk 0..19 (compile-time per t given q)
        const bool valid = (wi > 0 || ch >= 2) && (wi < 7 || ch < 18);
        if (valid) {
            unsigned dst = (unsigned)__cvta_generic_to_shared(slotp + 4*ch);
            asm volatile("cp.async.cg.shared.global [%0], [%1], 16;\n"
                         :: "r"(dst), "l"(rowp + (64*wi - 8 + 4*ch)) : "memory");
        }
    }
    if (wi == 0) {
        #pragma unroll
        for (int s = 0; s < 2; ++s) {
            const int f = 2*q + s;         // halo float 0..7, col -8+f -> refl = 7-f
            unsigned dst = (unsigned)__cvta_generic_to_shared(slotp + f);
            asm volatile("cp.async.ca.shared.global [%0], [%1], 4;\n"
                         :: "r"(dst), "l"(rowp + (7 - f)) : "memory");
        }
    } else if (wi == 7) {
        #pragma unroll
        for (int s = 0; s < 2; ++s) {
            const int f = 2*q + s;         // col 512+f -> refl = 511-f
            unsigned dst = (unsigned)__cvta_generic_to_shared(slotp + 72 + f);
            asm volatile("cp.async.ca.shared.global [%0], [%1], 4;\n"
                         :: "r"(dst), "l"(rowp + (511 - f)) : "memory");
        }
    }
}

// branch-free horizontal filters: p points at this thread's center pair (w3,w4)
__device__ __forceinline__ void hfilt_row(const float* __restrict__ p,
                                          u64 g0p, u64 g1p, u64 g2p,
                                          u64 h0p, u64 h1p, u64 h2p, u64 h3p,
                                          u64& loxy, u64& hizw) {
    const u64 PA = *(const u64*)(p - 4);
    const u64 PB = *(const u64*)(p - 2);
    const u64 PC = *(const u64*)(p    );
    const u64 PD = *(const u64*)(p + 2);
    const u64 PE = *(const u64*)(p + 4);
    float am, a0, b1, b2, c3, c4, d5, d6, e7, e8;
    upk(PA, am, a0); upk(PB, b1, b2); upk(PC, c3, c4);
    upk(PD, d5, d6); upk(PE, e7, e8);
    const u64 S1 = add2(PB, PD);                  // (w1+w5, w2+w6)
    const u64 S2 = pk(b2 + c4, c3 + d5);          // (w2+w4, w3+w5)
    const u64 T1 = pk(a0 + d6, b1 + e7);          // (w0+w6, w1+w7)
    loxy = fma2(S1, g0p, fma2(S2, g1p, mul2(PC, g2p)));
    hizw = fma2(T1, h0p, fma2(S1, h1p, fma2(S2, h2p, mul2(PC, h3p))));
}

__global__ __launch_bounds__(NTHREADS, 4) void scat_kernel(
    const float* __restrict__ x,
    float* __restrict__ out)
{
    extern __shared__ float smem[];        // [NWARP][NSLOT][SEGW]

    const int tid  = threadIdx.x;
    const int wi   = tid >> 5;
    const int lane = tid & 31;
    const int img  = blockIdx.z;
    const int OY0  = blockIdx.y * TILE_OY;
    const float* __restrict__ xin = x + (size_t)img * (512*512);
    float* seg = smem + wi * (NSLOT*SEGW);

    const int b_  = img / 3;
    const int ch_ = img % 3;
    const int c   = 32*wi + lane;
    float* o = out + (((size_t)b_*21 + ch_)*256 + OY0)*256 + c;
    const size_t cs = (size_t)3*256*256;

    const u64 g0p = pk(G0, G0), g1p = pk(G1, G1), g2p = pk(G2, G2);
    const u64 h0p = pk(H0, H0), h1p = pk(H1, H1), h2p = pk(H2, H2), h3p = pk(H3, H3);

    const int R = 2*OY0 - 3;               // input row = R + m, m = 0..37
    const int cofs = 8 + 2*lane;

    // ---- prologue: stage rows m=0..13 (rows 6..13 staged twice, identical bytes) ----
    stage8(xin, seg, lane, wi, R, 0);
    stage8(xin, seg, lane, wi, R, 6);
    commit_group();
    wait_all();
    __syncwarp();

    u64 rxy[8], rzw[8];
    #pragma unroll
    for (int j = 0; j < 6; j++)
        hfilt_row(seg + j*SEGW + cofs, g0p, g1p, g2p, h0p, h1p, h2p, h3p,
                  rxy[j], rzw[j]);

    #pragma unroll 1
    for (int i = 0; i < 4; ++i) {          // 4 output rows per iteration
        if (i > 0) {                       // rows 6+8i..13+8i (staged at iter i-1) landed
            wait_all();
            __syncwarp();
        }
        if (i < 3) {                       // stage rows 14+8i..21+8i for iter i+1
            stage8(xin, seg, lane, wi, R, 14 + 8*i);
            commit_group();
        }

        #pragma unroll
        for (int u = 0; u < 4; ++u) {
            const int m6 = 8*i + 6 + 2*u;  // two new rows completing window m..m+7
            hfilt_row(seg + ((m6    ) & (NSLOT-1))*SEGW + cofs,
                      g0p, g1p, g2p, h0p, h1p, h2p, h3p,
                      rxy[(6 + 2*u) & 7], rzw[(6 + 2*u) & 7]);
            hfilt_row(seg + ((m6 + 1) & (NSLOT-1))*SEGW + cofs,
                      g0p, g1p, g2p, h0p, h1p, h2p, h3p,
                      rxy[(7 + 2*u) & 7], rzw[(7 + 2*u) & 7]);

            const int w0 = 2*u;            // compile-time window base

            float llp, m15, m165, m45, m135, m75, m105;
            #pragma unroll
            for (int plane = 0; plane < 2; plane++) {
                const u64* r = plane ? rzw : rxy;
                const u64 r0 = r[(w0 + 0) & 7], r1 = r[(w0 + 1) & 7];
                const u64 r2 = r[(w0 + 2) & 7], r3 = r[(w0 + 3) & 7];
                const u64 r4 = r[(w0 + 4) & 7], r5 = r[(w0 + 5) & 7];
                const u64 r6 = r[(w0 + 6) & 7], r7 = r[(w0 + 7) & 7];

                const u64 A06 = add2(r0, r6), A15 = add2(r1, r5), A24 = add2(r2, r4);
                const u64 A17 = add2(r1, r7), A26 = add2(r2, r6), A35 = add2(r3, r5);

                const u64 F0 = fma2(A06, h0p, fma2(A15, h1p, fma2(A24, h2p, mul2(r3, h3p))));
                const u64 F1 = fma2(A17, h0p, fma2(A26, h1p, fma2(A35, h2p, mul2(r4, h3p))));

                float f0x, f0y, f1x, f1y;
                upk(F0, f0x, f0y); upk(F1, f1x, f1y);

                if (plane == 0) {
                    m15  = bandmag(f0x - f1y, f0y + f1x);
                    m165 = bandmag(f0x + f1y, f0y - f1x);
                    const u64 B  = add2(A15, A26);
                    const u64 Cs = add2(A24, A35);
                    const u64 Ds = add2(r3, r4);
                    const u64 LLs = fma2(B, g0p, fma2(Cs, g1p, mul2(Ds, g2p)));
                    float s0, s1;
                    upk(LLs, s0, s1);
                    llp = 0.25f * (s0 + s1);
                } else {
                    m45  = bandmag(f0x - f1y, f0y + f1x);
                    m135 = bandmag(f0x + f1y, f0y - f1x);
                    const u64 E0 = fma2(A15, g0p, fma2(A24, g1p, mul2(r3, g2p)));
                    const u64 E1 = fma2(A26, g0p, fma2(A35, g1p, mul2(r4, g2p)));
                    float e0x, e0y, e1x, e1y;
                    upk(E0, e0x, e0y); upk(E1, e1x, e1y);
                    m75  = bandmag(e0x - e1y, e0y + e1x);
                    m105 = bandmag(e0x + e1y, e0y - e1x);
                }
            }

            o[0]    = llp;
            o[1*cs] = m15;
            o[2*cs] = m45;
            o[3*cs] = m75;
            o[4*cs] = m105;
            o[5*cs] = m135;
            o[6*cs] = m165;
            o += 256;                      // next output row
        }
    }
}

extern "C" void kernel_launch(void* const* d_in, const int* in_sizes, int n_in,
                              void* d_out, int out_size) {
    const float* x = (const float*)d_in[0];
    float* out = (float*)d_out;

    cudaFuncSetAttribute(scat_kernel,
                         cudaFuncAttributeMaxDynamicSharedMemorySize, SMEM_BYTES);

    dim3 grid(1, 256/TILE_OY, 96);         // (1, 16, 96)
    scat_kernel<<<grid, NTHREADS, SMEM_BYTES>>>(x, out);
}

// round 16
// speedup vs baseline: 1.1771x; 1.0056x over previous
#include <cuda_runtime.h>
#include <math.h>

// Fused DTCWT scattering layer, round 16: round 15 + exact (non-duplicated) prologue staging.
//  - each warp owns 32 pair-columns; private 16-slot smem ring of 80-float segments
//  - staging: lane -> row j=lane>>2, chunks ch=(lane&3)+4t (5 x 16B cp.async/lane, shift/mask only)
//  - stageN<NR>: lanes with j>=NR idle -> prologue stages rows 0..13 exactly once
//  - edge halos (warps 0,7): 2 x 4B reflected cp.async per lane
//  - no __syncthreads; wait_group + __syncwarp only
// x: (32,3,512,512) f32 -> out: (32,21,256,256) f32

#define TILE_OY 16
#define NTHREADS 256
#define NWARP 8
#define SEGW 80                    // 8 halo | 64 data | 8 halo (floats)
#define NSLOT 16
#define SMEM_BYTES (NWARP*NSLOT*SEGW*4)   // 40960

// h0: [-0.05, 0.25, 0.6, 0.25, -0.05]  (symmetric)
#define G0 (-0.05f)
#define G1 (0.25f)
#define G2 (0.6f)
// h1: [-0.0107143, 0.0535714, 0.2607143, -0.6071429, ...] (symmetric)
#define H0 (-0.0107143f)
#define H1 (0.0535714f)
#define H2 (0.2607143f)
#define H3 (-0.6071429f)

typedef unsigned long long u64;

__device__ __forceinline__ u64 pk(float lo, float hi) {
    u64 r; asm("mov.b64 %0,{%1,%2};" : "=l"(r) : "f"(lo), "f"(hi)); return r;
}
__device__ __forceinline__ void upk(u64 v, float& a, float& b) {
    asm("mov.b64 {%0,%1},%2;" : "=f"(a), "=f"(b) : "l"(v));
}
__device__ __forceinline__ u64 add2(u64 a, u64 b) {
    u64 r; asm("add.rn.f32x2 %0,%1,%2;" : "=l"(r) : "l"(a), "l"(b)); return r;
}
__device__ __forceinline__ u64 mul2(u64 a, u64 b) {
    u64 r; asm("mul.rn.f32x2 %0,%1,%2;" : "=l"(r) : "l"(a), "l"(b)); return r;
}
__device__ __forceinline__ u64 fma2(u64 a, u64 b, u64 c) {
    u64 r; asm("fma.rn.f32x2 %0,%1,%2,%3;" : "=l"(r) : "l"(a), "l"(b), "l"(c)); return r;
}

__device__ __forceinline__ int refl(int i) {
    i = (i < 0) ? (-i - 1) : i;
    return (i > 511) ? (1023 - i) : i;
}
__device__ __forceinline__ float sqrt_approx(float v) {
    float r; asm("sqrt.approx.f32 %0, %1;" : "=f"(r) : "f"(v)); return r;
}
// band value = sqrt((re^2+im^2)/2 + 1e-4) - 0.01  (1/sqrt2 folded in)
__device__ __forceinline__ float bandmag(float re, float im) {
    return sqrt_approx(0.5f * fmaf(re, re, fmaf(im, im, 2e-4f))) - 0.01f;
}

__device__ __forceinline__ void commit_group() {
    asm volatile("cp.async.commit_group;\n" ::: "memory");
}
__device__ __forceinline__ void wait_all() {
    asm volatile("cp.async.wait_group 0;\n" ::: "memory");
}

// Stage NR rows (window indices m0..m0+NR-1) into this warp's private ring.
// lane -> row j = lane>>2 (4 lanes per row); lanes with j >= NR do nothing.
// Each active lane copies 5 16B chunks ch=(lane&3)+4t; edge warps add 2 4B halos.
template<int NR>
__device__ __forceinline__ void stageN(const float* __restrict__ xin, float* seg,
                                       int lane, int wi, int R, int m0) {
    const int j = lane >> 2;
    if (NR < 8 && j >= NR) return;
    const int q = lane & 3;
    const int m = m0 + j;
    const int gy = refl(R + m);
    const float* rowp = xin + (size_t)gy * 512;
    float* slotp = seg + (m & (NSLOT-1)) * SEGW;

    #pragma unroll
    for (int t = 0; t < 5; ++t) {
        const int ch = q + 4*t;            // 16B chunk 0..19
        const bool valid = (wi > 0 || ch >= 2) && (wi < 7 || ch < 18);
        if (valid) {
            unsigned dst = (unsigned)__cvta_generic_to_shared(slotp + 4*ch);
            asm volatile("cp.async.cg.shared.global [%0], [%1], 16;\n"
                         :: "r"(dst), "l"(rowp + (64*wi - 8 + 4*ch)) : "memory");
        }
    }
    if (wi == 0) {
        #pragma unroll
        for (int s = 0; s < 2; ++s) {
            const int f = 2*q + s;         // halo float 0..7, col -8+f -> refl = 7-f
            unsigned dst = (unsigned)__cvta_generic_to_shared(slotp + f);
            asm volatile("cp.async.ca.shared.global [%0], [%1], 4;\n"
                         :: "r"(dst), "l"(rowp + (7 - f)) : "memory");
        }
    } else if (wi == 7) {
        #pragma unroll
        for (int s = 0; s < 2; ++s) {
            const int f = 2*q + s;         // col 512+f -> refl = 511-f
            unsigned dst = (unsigned)__cvta_generic_to_shared(slotp + 72 + f);
            asm volatile("cp.async.ca.shared.global [%0], [%1], 4;\n"
                         :: "r"(dst), "l"(rowp + (511 - f)) : "memory");
        }
    }
}

// branch-free horizontal filters: p points at this thread's center pair (w3,w4)
__device__ __forceinline__ void hfilt_row(const float* __restrict__ p,
                                          u64 g0p, u64 g1p, u64 g2p,
                                          u64 h0p, u64 h1p, u64 h2p, u64 h3p,
                                          u64& loxy, u64& hizw) {
    const u64 PA = *(const u64*)(p - 4);
    const u64 PB = *(const u64*)(p - 2);
    const u64 PC = *(const u64*)(p    );
    const u64 PD = *(const u64*)(p + 2);
    const u64 PE = *(const u64*)(p + 4);
    float am, a0, b1, b2, c3, c4, d5, d6, e7, e8;
    upk(PA, am, a0); upk(PB, b1, b2); upk(PC, c3, c4);
    upk(PD, d5, d6); upk(PE, e7, e8);
    const u64 S1 = add2(PB, PD);                  // (w1+w5, w2+w6)
    const u64 S2 = pk(b2 + c4, c3 + d5);          // (w2+w4, w3+w5)
    const u64 T1 = pk(a0 + d6, b1 + e7);          // (w0+w6, w1+w7)
    loxy = fma2(S1, g0p, fma2(S2, g1p, mul2(PC, g2p)));
    hizw = fma2(T1, h0p, fma2(S1, h1p, fma2(S2, h2p, mul2(PC, h3p))));
}

__global__ __launch_bounds__(NTHREADS, 4) void scat_kernel(
    const float* __restrict__ x,
    float* __restrict__ out)
{
    extern __shared__ float smem[];        // [NWARP][NSLOT][SEGW]

    const int tid  = threadIdx.x;
    const int wi   = tid >> 5;
    const int lane = tid & 31;
    const int img  = blockIdx.z;
    const int OY0  = blockIdx.y * TILE_OY;
    const float* __restrict__ xin = x + (size_t)img * (512*512);
    float* seg = smem + wi * (NSLOT*SEGW);

    const int b_  = img / 3;
    const int ch_ = img % 3;
    const int c   = 32*wi + lane;
    float* o = out + (((size_t)b_*21 + ch_)*256 + OY0)*256 + c;
    const size_t cs = (size_t)3*256*256;

    const u64 g0p = pk(G0, G0), g1p = pk(G1, G1), g2p = pk(G2, G2);
    const u64 h0p = pk(H0, H0), h1p = pk(H1, H1), h2p = pk(H2, H2), h3p = pk(H3, H3);

    const int R = 2*OY0 - 3;               // input row = R + m, m = 0..37
    const int cofs = 8 + 2*lane;

    // ---- prologue: stage rows m=0..13 exactly once ----
    stageN<8>(xin, seg, lane, wi, R, 0);
    stageN<6>(xin, seg, lane, wi, R, 8);
    commit_group();
    wait_all();
    __syncwarp();

    u64 rxy[8], rzw[8];
    #pragma unroll
    for (int j = 0; j < 6; j++)
        hfilt_row(seg + j*SEGW + cofs, g0p, g1p, g2p, h0p, h1p, h2p, h3p,
                  rxy[j], rzw[j]);

    #pragma unroll 1
    for (int i = 0; i < 4; ++i) {          // 4 output rows per iteration
        if (i > 0) {                       // rows 6+8i..13+8i (staged at iter i-1) landed
            wait_all();
            __syncwarp();
        }
        if (i < 3) {                       // stage rows 14+8i..21+8i for iter i+1
            stageN<8>(xin, seg, lane, wi, R, 14 + 8*i);
            commit_group();
        }

        #pragma unroll
        for (int u = 0; u < 4; ++u) {
            const int m6 = 8*i + 6 + 2*u;  // two new rows completing window m..m+7
            hfilt_row(seg + ((m6    ) & (NSLOT-1))*SEGW + cofs,
                      g0p, g1p, g2p, h0p, h1p, h2p, h3p,
                      rxy[(6 + 2*u) & 7], rzw[(6 + 2*u) & 7]);
            hfilt_row(seg + ((m6 + 1) & (NSLOT-1))*SEGW + cofs,
                      g0p, g1p, g2p, h0p, h1p, h2p, h3p,
                      rxy[(7 + 2*u) & 7], rzw[(7 + 2*u) & 7]);

            const int w0 = 2*u;            // compile-time window base

            float llp, m15, m165, m45, m135, m75, m105;
            #pragma unroll
            for (int plane = 0; plane < 2; plane++) {
                const u64* r = plane ? rzw : rxy;
                const u64 r0 = r[(w0 + 0) & 7], r1 = r[(w0 + 1) & 7];
                const u64 r2 = r[(w0 + 2) & 7], r3 = r[(w0 + 3) & 7];
                const u64 r4 = r[(w0 + 4) & 7], r5 = r[(w0 + 5) & 7];
                const u64 r6 = r[(w0 + 6) & 7], r7 = r[(w0 + 7) & 7];

                const u64 A06 = add2(r0, r6), A15 = add2(r1, r5), A24 = add2(r2, r4);
                const u64 A17 = add2(r1, r7), A26 = add2(r2, r6), A35 = add2(r3, r5);

                const u64 F0 = fma2(A06, h0p, fma2(A15, h1p, fma2(A24, h2p, mul2(r3, h3p))));
                const u64 F1 = fma2(A17, h0p, fma2(A26, h1p, fma2(A35, h2p, mul2(r4, h3p))));

                float f0x, f0y, f1x, f1y;
                upk(F0, f0x, f0y); upk(F1, f1x, f1y);

                if (plane == 0) {
                    m15  = bandmag(f0x - f1y, f0y + f1x);
                    m165 = bandmag(f0x + f1y, f0y - f1x);
                    const u64 B  = add2(A15, A26);
                    const u64 Cs = add2(A24, A35);
                    const u64 Ds = add2(r3, r4);
                    const u64 LLs = fma2(B, g0p, fma2(Cs, g1p, mul2(Ds, g2p)));
                    float s0, s1;
                    upk(LLs, s0, s1);
                    llp = 0.25f * (s0 + s1);
                } else {
                    m45  = bandmag(f0x - f1y, f0y + f1x);
                    m135 = bandmag(f0x + f1y, f0y - f1x);
                    const u64 E0 = fma2(A15, g0p, fma2(A24, g1p, mul2(r3, g2p)));
                    const u64 E1 = fma2(A26, g0p, fma2(A35, g1p, mul2(r4, g2p)));
                    float e0x, e0y, e1x, e1y;
                    upk(E0, e0x, e0y); upk(E1, e1x, e1y);
                    m75  = bandmag(e0x - e1y, e0y + e1x);
                    m105 = bandmag(e0x + e1y, e0y - e1x);
                }
            }

            o[0]    = llp;
            o[1*cs] = m15;
            o[2*cs] = m45;
            o[3*cs] = m75;
            o[4*cs] = m105;
            o[5*cs] = m135;
            o[6*cs] = m165;
            o += 256;                      // next output row
        }
    }
}

extern "C" void kernel_launch(void* const* d_in, const int* in_sizes, int n_in,
                              void* d_out, int out_size) {
    const float* x = (const float*)d_in[0];
    float* out = (float*)d_out;

    cudaFuncSetAttribute(scat_kernel,
                         cudaFuncAttributeMaxDynamicSharedMemorySize, SMEM_BYTES);

    dim3 grid(1, 256/TILE_OY, 96);         // (1, 16, 96)
    scat_kernel<<<grid, NTHREADS, SMEM_BYTES>>>(x, out);
}

// round 17
// speedup vs baseline: 1.2674x; 1.0767x over previous
#include <cuda_runtime.h>
#include <math.h>

// Fused DTCWT scattering layer, round 17: R12 base (best wall time) + half-height tiles
// to cut wave-quantization drain (1536 CTAs/2.59 waves -> 3072 CTAs/5.19 waves).
//  - 16-slot smem ring of PADDED rows (4+512+4); pads via 4B cp.async
//  - TILE_OY=8: prologue stages m=0..13, one mid-tile stage of m=14..21; 2 barriers/tile
//  - packed f32x2 filters with symmetric-tap sharing; pooled-LL direct filter
// x: (32,3,512,512) f32 -> out: (32,21,256,256) f32

#define TILE_OY 8
#define NTHREADS 256
#define ROWSTRIDE 524              // 4 pad | 512 data | 4 pad | 4 spare (floats)
#define NSLOT 16
#define SMEM_BYTES (NSLOT*ROWSTRIDE*4)   // 33536

// h0: [-0.05, 0.25, 0.6, 0.25, -0.05]  (symmetric)
#define G0 (-0.05f)
#define G1 (0.25f)
#define G2 (0.6f)
// h1: [-0.0107143, 0.0535714, 0.2607143, -0.6071429, ...] (symmetric)
#define H0 (-0.0107143f)
#define H1 (0.0535714f)
#define H2 (0.2607143f)
#define H3 (-0.6071429f)

typedef unsigned long long u64;

__device__ __forceinline__ u64 pk(float lo, float hi) {
    u64 r; asm("mov.b64 %0,{%1,%2};" : "=l"(r) : "f"(lo), "f"(hi)); return r;
}
__device__ __forceinline__ void upk(u64 v, float& a, float& b) {
    asm("mov.b64 {%0,%1},%2;" : "=f"(a), "=f"(b) : "l"(v));
}
__device__ __forceinline__ u64 add2(u64 a, u64 b) {
    u64 r; asm("add.rn.f32x2 %0,%1,%2;" : "=l"(r) : "l"(a), "l"(b)); return r;
}
__device__ __forceinline__ u64 mul2(u64 a, u64 b) {
    u64 r; asm("mul.rn.f32x2 %0,%1,%2;" : "=l"(r) : "l"(a), "l"(b)); return r;
}
__device__ __forceinline__ u64 fma2(u64 a, u64 b, u64 c) {
    u64 r; asm("fma.rn.f32x2 %0,%1,%2,%3;" : "=l"(r) : "l"(a), "l"(b), "l"(c)); return r;
}

__device__ __forceinline__ int refl(int i) {
    i = (i < 0) ? (-i - 1) : i;
    return (i > 511) ? (1023 - i) : i;
}
__device__ __forceinline__ float sqrt_approx(float v) {
    float r; asm("sqrt.approx.f32 %0, %1;" : "=f"(r) : "f"(v)); return r;
}
// band value = sqrt((re^2+im^2)/2 + 1e-4) - 0.01  (1/sqrt2 folded in)
__device__ __forceinline__ float bandmag(float re, float im) {
    return sqrt_approx(0.5f * fmaf(re, re, fmaf(im, im, 2e-4f))) - 0.01f;
}

__device__ __forceinline__ void commit_group() {
    asm volatile("cp.async.commit_group;\n" ::: "memory");
}
__device__ __forceinline__ void wait_all() {
    asm volatile("cp.async.wait_group 0;\n" ::: "memory");
}

// stage nr rows starting at window-index m0 (nr even, nr<=14):
//  - row bodies: nr/2 x 16B cp.async.cg per thread
//  - reflected pads (8 per row): one 4B cp.async.ca per thread (t < 8*nr)
__device__ __forceinline__ void stage_rows(const float* __restrict__ xin, float* srow,
                                           int t, int R, int m0, int nr) {
    const int rl = t >> 7, chunk = t & 127;
    #pragma unroll
    for (int j = 0; j < 7; ++j) {
        if (j >= nr/2) break;
        const int m  = m0 + 2*j + rl;
        const int gy = refl(R + m);
        const float* src = xin + (size_t)gy*512 + chunk*4;
        unsigned dst = (unsigned)__cvta_generic_to_shared(
            &srow[(m & (NSLOT-1))*ROWSTRIDE + 4 + chunk*4]);
        asm volatile("cp.async.cg.shared.global [%0], [%1], 16;\n" :: "r"(dst), "l"(src) : "memory");
    }
    if (t < 8*nr) {
        const int k = t >> 3, pp = t & 7;
        const int m  = m0 + k;
        const int gy = refl(R + m);
        const int srccol = (pp < 4) ? (3 - pp) : (515 - pp);
        const int dstofs = (pp < 4) ? pp : (512 + pp);
        const float* src = xin + (size_t)gy*512 + srccol;
        unsigned dst = (unsigned)__cvta_generic_to_shared(
            &srow[(m & (NSLOT-1))*ROWSTRIDE + dstofs]);
        asm volatile("cp.async.ca.shared.global [%0], [%1], 4;\n" :: "r"(dst), "l"(src) : "memory");
    }
}

// branch-free horizontal filters: p = row_base + 4 + 2c
__device__ __forceinline__ void hfilt_row(const float* __restrict__ p,
                                          u64 g0p, u64 g1p, u64 g2p,
                                          u64 h0p, u64 h1p, u64 h2p, u64 h3p,
                                          u64& loxy, u64& hizw) {
    const u64 PA = *(const u64*)(p - 4);
    const u64 PB = *(const u64*)(p - 2);
    const u64 PC = *(const u64*)(p    );
    const u64 PD = *(const u64*)(p + 2);
    const u64 PE = *(const u64*)(p + 4);
    float am, a0, b1, b2, c3, c4, d5, d6, e7, e8;
    upk(PA, am, a0); upk(PB, b1, b2); upk(PC, c3, c4);
    upk(PD, d5, d6); upk(PE, e7, e8);
    const u64 S1 = add2(PB, PD);                  // (w1+w5, w2+w6)
    const u64 S2 = pk(b2 + c4, c3 + d5);          // (w2+w4, w3+w5)
    const u64 T1 = pk(a0 + d6, b1 + e7);          // (w0+w6, w1+w7)
    loxy = fma2(S1, g0p, fma2(S2, g1p, mul2(PC, g2p)));
    hizw = fma2(T1, h0p, fma2(S1, h1p, fma2(S2, h2p, mul2(PC, h3p))));
}

__global__ __launch_bounds__(NTHREADS, 4) void scat_kernel(
    const float* __restrict__ x,
    float* __restrict__ out)
{
    extern __shared__ float srow[];        // [NSLOT][ROWSTRIDE]

    const int c   = threadIdx.x;           // pair-column 0..255
    const int img = blockIdx.z;
    const int OY0 = blockIdx.y * TILE_OY;
    const float* __restrict__ xin = x + (size_t)img * (512*512);

    const int b_  = img / 3;
    const int ch_ = img % 3;
    float* o = out + (((size_t)b_*21 + ch_)*256 + OY0)*256 + c;   // walked by +256/row
    const size_t cs = (size_t)3*256*256;

    const u64 g0p = pk(G0, G0), g1p = pk(G1, G1), g2p = pk(G2, G2);
    const u64 h0p = pk(H0, H0), h1p = pk(H1, H1), h2p = pk(H2, H2), h3p = pk(H3, H3);

    const int R = 2*OY0 - 3;               // input row = R + m, m = 0..21
    const int cofs = 4 + 2*c;

    // ---- prologue: stage rows m=0..13, ring-fill m=0..5 ----
    stage_rows(xin, srow, c, R, 0, 14); commit_group();
    wait_all();
    __syncthreads();

    u64 rxy[8], rzw[8];
    #pragma unroll
    for (int j = 0; j < 6; j++)
        hfilt_row(&srow[j*ROWSTRIDE + cofs], g0p, g1p, g2p, h0p, h1p, h2p, h3p,
                  rxy[j], rzw[j]);
    __syncthreads();                       // slots 0..5 free before iter-0 staging

    #pragma unroll 1
    for (int i = 0; i < 2; ++i) {          // 4 output rows per iteration
        if (i > 0) {                       // rows 14..21 (staged at iter 0) landed
            wait_all();
            __syncthreads();
        }
        if (i < 1) {                       // stage rows 14..21 for iter 1
            stage_rows(xin, srow, c, R, 14, 8);
            commit_group();
        }

        #pragma unroll
        for (int u = 0; u < 4; ++u) {
            const int m6 = 8*i + 6 + 2*u;  // two new rows completing window m..m+7
            hfilt_row(&srow[((m6    ) & (NSLOT-1))*ROWSTRIDE + cofs],
                      g0p, g1p, g2p, h0p, h1p, h2p, h3p,
                      rxy[(6 + 2*u) & 7], rzw[(6 + 2*u) & 7]);
            hfilt_row(&srow[((m6 + 1) & (NSLOT-1))*ROWSTRIDE + cofs],
                      g0p, g1p, g2p, h0p, h1p, h2p, h3p,
                      rxy[(7 + 2*u) & 7], rzw[(7 + 2*u) & 7]);

            const int w0 = 2*u;            // compile-time window base

            float llp, m15, m165, m45, m135, m75, m105;
            #pragma unroll
            for (int plane = 0; plane < 2; plane++) {
                const u64* r = plane ? rzw : rxy;
                const u64 r0 = r[(w0 + 0) & 7], r1 = r[(w0 + 1) & 7];
                const u64 r2 = r[(w0 + 2) & 7], r3 = r[(w0 + 3) & 7];
                const u64 r4 = r[(w0 + 4) & 7], r5 = r[(w0 + 5) & 7];
                const u64 r6 = r[(w0 + 6) & 7], r7 = r[(w0 + 7) & 7];

                const u64 A06 = add2(r0, r6), A15 = add2(r1, r5), A24 = add2(r2, r4);
                const u64 A17 = add2(r1, r7), A26 = add2(r2, r6), A35 = add2(r3, r5);

                const u64 F0 = fma2(A06, h0p, fma2(A15, h1p, fma2(A24, h2p, mul2(r3, h3p))));
                const u64 F1 = fma2(A17, h0p, fma2(A26, h1p, fma2(A35, h2p, mul2(r4, h3p))));

                float f0x, f0y, f1x, f1y;
                upk(F0, f0x, f0y); upk(F1, f1x, f1y);

                if (plane == 0) {
                    m15  = bandmag(f0x - f1y, f0y + f1x);
                    m165 = bandmag(f0x + f1y, f0y - f1x);
                    const u64 B  = add2(A15, A26);
                    const u64 Cs = add2(A24, A35);
                    const u64 Ds = add2(r3, r4);
                    const u64 LLs = fma2(B, g0p, fma2(Cs, g1p, mul2(Ds, g2p)));
                    float s0, s1;
                    upk(LLs, s0, s1);
                    llp = 0.25f * (s0 + s1);
                } else {
                    m45  = bandmag(f0x - f1y, f0y + f1x);
                    m135 = bandmag(f0x + f1y, f0y - f1x);
                    const u64 E0 = fma2(A15, g0p, fma2(A24, g1p, mul2(r3, g2p)));
                    const u64 E1 = fma2(A26, g0p, fma2(A35, g1p, mul2(r4, g2p)));
                    float e0x, e0y, e1x, e1y;
                    upk(E0, e0x, e0y); upk(E1, e1x, e1y);
                    m75  = bandmag(e0x - e1y, e0y + e1x);
                    m105 = bandmag(e0x + e1y, e0y - e1x);
                }
            }

            o[0]    = llp;
            o[1*cs] = m15;
            o[2*cs] = m45;
            o[3*cs] = m75;
            o[4*cs] = m105;
            o[5*cs] = m135;
            o[6*cs] = m165;
            o += 256;                      // next output row
        }
    }
}

extern "C" void kernel_launch(void* const* d_in, const int* in_sizes, int n_in,
                              void* d_out, int out_size) {
    const float* x = (const float*)d_in[0];
    float* out = (float*)d_out;

    cudaFuncSetAttribute(scat_kernel,
                         cudaFuncAttributeMaxDynamicSharedMemorySize, SMEM_BYTES);

    dim3 grid(1, 256/TILE_OY, 96);         // (1, 32, 96) = 3072 CTAs
    scat_kernel<<<grid, NTHREADS, SMEM_BYTES>>>(x, out);
}